// round 2
// baseline (speedup 1.0000x reference)
#include <cuda_runtime.h>
#include <cstdint>

#define NN 100000
#define EE 600000
#define PP 100000
#define D  128

// scratch (static device globals — no allocation allowed)
__device__ float g_hA[(size_t)NN * D];
__device__ float g_hB[(size_t)NN * D];
__device__ float g_agg[(size_t)NN * D];
__device__ float g_cnt[NN];

// ---------------------------------------------------------------------------
// Edge scatter: agg[dst] += w * h[src], cnt[dst] += 1
// 32 threads per edge, each handles one float4 (4 features)
// ---------------------------------------------------------------------------
__global__ void __launch_bounds__(256) edge_kernel(
    const int* __restrict__ src, const int* __restrict__ dst,
    const float* __restrict__ w, const float* __restrict__ h)
{
    int t = blockIdx.x * blockDim.x + threadIdx.x;
    int e = t >> 5;
    if (e >= EE) return;
    int lane = t & 31;
    int s = __ldg(src + e);
    int d = __ldg(dst + e);
    float we = __ldg(w + e);
    float4 v = __ldg((const float4*)(h + (size_t)s * D) + lane);
    v.x *= we; v.y *= we; v.z *= we; v.w *= we;
    float* a = g_agg + (size_t)d * D + lane * 4;
    asm volatile("red.global.add.v4.f32 [%0], {%1,%2,%3,%4};"
                 :: "l"(a), "f"(v.x), "f"(v.y), "f"(v.z), "f"(v.w) : "memory");
    if (lane == 0) atomicAdd(g_cnt + d, 1.0f);
}

// ---------------------------------------------------------------------------
// Fused SAGE node update:
//   out = [h | agg/max(cnt,1)] @ [Wself ; Wneigh] + b  (optional ReLU)
// Tiled fp32 GEMM: 64 rows x 128 cols per block, K=256, BK=16, 256 threads,
// 8x4 register micro-tile per thread.
// ---------------------------------------------------------------------------
#define BM 64
#define BK 16

__global__ void __launch_bounds__(256) sage_node_kernel(
    const float* __restrict__ h_in,
    const float* __restrict__ Wself, const float* __restrict__ Wneigh,
    const float* __restrict__ bias,
    float* __restrict__ h_out, int do_relu)
{
    __shared__ float As[BM][BK + 4];     // [64][20] — conflict-free, float4-aligned rows
    __shared__ float Bs[BK][128];
    __shared__ float rcp_s[BM];

    int t = threadIdx.x;
    int row_blk = blockIdx.x * BM;

    if (t < BM) {
        int g = row_blk + t;
        float c = (g < NN) ? g_cnt[g] : 1.0f;
        rcp_s[t] = 1.0f / fmaxf(c, 1.0f);
    }
    __syncthreads();

    int arow = t >> 2;      // 0..63
    int aq   = t & 3;       // which float4 of the 16-wide k chunk
    int tm   = t >> 5;      // 0..7
    int tn   = t & 31;      // 0..31
    int r0   = tm * 8;
    int c0   = tn * 4;

    float acc[8][4];
    #pragma unroll
    for (int r = 0; r < 8; r++)
        #pragma unroll
        for (int c = 0; c < 4; c++) acc[r][c] = 0.0f;

    #pragma unroll 1
    for (int kb = 0; kb < 256; kb += BK) {
        // --- load A tile (64 x 16): one float4 per thread ---
        {
            int g = row_blk + arow;
            int k0 = kb + aq * 4;
            float4 v = make_float4(0.f, 0.f, 0.f, 0.f);
            if (g < NN) {
                if (k0 < 128) {
                    v = *(const float4*)(h_in + (size_t)g * D + k0);
                } else {
                    v = *(const float4*)(g_agg + (size_t)g * D + (k0 - 128));
                    float rc = rcp_s[arow];
                    v.x *= rc; v.y *= rc; v.z *= rc; v.w *= rc;
                }
            }
            *(float4*)&As[arow][aq * 4] = v;
        }
        // --- load B tile (16 x 128): two float4 per thread ---
        #pragma unroll
        for (int i = 0; i < 2; i++) {
            int cidx = t + i * 256;          // 0..511 float4s
            int kk = cidx >> 5;              // 0..15
            int j4 = cidx & 31;              // 0..31
            int kg = kb + kk;
            const float* W = (kg < 128) ? Wself : Wneigh;
            float4 bv = __ldg((const float4*)(W + (size_t)(kg & 127) * D) + j4);
            *(float4*)&Bs[kk][j4 * 4] = bv;
        }
        __syncthreads();

        #pragma unroll
        for (int k = 0; k < BK; k++) {
            float a[8];
            #pragma unroll
            for (int r = 0; r < 8; r++) a[r] = As[r0 + r][k];
            float4 b = *(float4*)&Bs[k][c0];
            #pragma unroll
            for (int r = 0; r < 8; r++) {
                acc[r][0] += a[r] * b.x;
                acc[r][1] += a[r] * b.y;
                acc[r][2] += a[r] * b.z;
                acc[r][3] += a[r] * b.w;
            }
        }
        __syncthreads();
    }

    float4 bb = __ldg((const float4*)(bias + c0));
    #pragma unroll
    for (int r = 0; r < 8; r++) {
        int g = row_blk + r0 + r;
        if (g < NN) {
            float4 o;
            o.x = acc[r][0] + bb.x;
            o.y = acc[r][1] + bb.y;
            o.z = acc[r][2] + bb.z;
            o.w = acc[r][3] + bb.w;
            if (do_relu) {
                o.x = fmaxf(o.x, 0.f); o.y = fmaxf(o.y, 0.f);
                o.z = fmaxf(o.z, 0.f); o.w = fmaxf(o.w, 0.f);
            }
            *(float4*)(h_out + (size_t)g * D + c0) = o;
        }
    }
}

// ---------------------------------------------------------------------------
// Fused link predictor: 64 pairs per block.
//   z = h[a]*h[b]; z1 = relu(z@pw1+pb1); z2 = relu(z1@pw2+pb2); out = z2@pw3+pb3
// Everything stays in smem: Zin/Zout (64x132) + Ws (128x128).
// ---------------------------------------------------------------------------
#define ZPAD 132
#define SMEM_PRED ((2 * 64 * ZPAD + 128 * 128) * 4)

__global__ void __launch_bounds__(256) pred_kernel(
    const float* __restrict__ h,
    const int* __restrict__ ia, const int* __restrict__ ib,
    const float* __restrict__ pw1, const float* __restrict__ pb1,
    const float* __restrict__ pw2, const float* __restrict__ pb2,
    const float* __restrict__ pw3, const float* __restrict__ pb3,
    float* __restrict__ out)
{
    extern __shared__ float sm[];
    float (*Zin)[ZPAD]  = (float(*)[ZPAD])sm;
    float (*Zout)[ZPAD] = (float(*)[ZPAD])(sm + 64 * ZPAD);
    float (*Ws)[128]    = (float(*)[128])(sm + 2 * 64 * ZPAD);

    int t = threadIdx.x;
    int p0 = blockIdx.x * 64;

    // --- stage 0: Zin = h[ia] * h[ib] ---
    {
        int zrow = t >> 2;
        int zq   = t & 3;
        int gp = p0 + zrow;
        bool valid = gp < PP;
        int sa = valid ? __ldg(ia + gp) : 0;
        int sb = valid ? __ldg(ib + gp) : 0;
        const float4* ha = (const float4*)(h + (size_t)sa * D);
        const float4* hb = (const float4*)(h + (size_t)sb * D);
        #pragma unroll
        for (int i = 0; i < 8; i++) {
            int q = zq + i * 4;
            float4 va = __ldg(ha + q);
            float4 vb = __ldg(hb + q);
            float4 z = make_float4(va.x * vb.x, va.y * vb.y, va.z * vb.z, va.w * vb.w);
            *(float4*)&Zin[zrow][q * 4] = z;
        }
    }
    // load pw1 into Ws
    #pragma unroll
    for (int i = 0; i < 16; i++) {
        int c = t + i * 256;
        ((float4*)&Ws[0][0])[c] = __ldg((const float4*)pw1 + c);
    }
    __syncthreads();

    int tm = t >> 5, tn = t & 31;
    int r0 = tm * 8, c0 = tn * 4;

    // --- stage 1: Zout = relu(Zin @ pw1 + pb1) ---
    {
        float acc[8][4];
        #pragma unroll
        for (int r = 0; r < 8; r++)
            #pragma unroll
            for (int c = 0; c < 4; c++) acc[r][c] = 0.f;
        #pragma unroll 8
        for (int k = 0; k < 128; k++) {
            float a[8];
            #pragma unroll
            for (int r = 0; r < 8; r++) a[r] = Zin[r0 + r][k];
            float4 b = *(float4*)&Ws[k][c0];
            #pragma unroll
            for (int r = 0; r < 8; r++) {
                acc[r][0] += a[r] * b.x; acc[r][1] += a[r] * b.y;
                acc[r][2] += a[r] * b.z; acc[r][3] += a[r] * b.w;
            }
        }
        float4 bb = __ldg((const float4*)(pb1 + c0));
        #pragma unroll
        for (int r = 0; r < 8; r++) {
            float4 o;
            o.x = fmaxf(acc[r][0] + bb.x, 0.f);
            o.y = fmaxf(acc[r][1] + bb.y, 0.f);
            o.z = fmaxf(acc[r][2] + bb.z, 0.f);
            o.w = fmaxf(acc[r][3] + bb.w, 0.f);
            *(float4*)&Zout[r0 + r][c0] = o;
        }
    }
    __syncthreads();
    // reload Ws = pw2
    #pragma unroll
    for (int i = 0; i < 16; i++) {
        int c = t + i * 256;
        ((float4*)&Ws[0][0])[c] = __ldg((const float4*)pw2 + c);
    }
    __syncthreads();

    // --- stage 2: Zin = relu(Zout @ pw2 + pb2) ---
    {
        float acc[8][4];
        #pragma unroll
        for (int r = 0; r < 8; r++)
            #pragma unroll
            for (int c = 0; c < 4; c++) acc[r][c] = 0.f;
        #pragma unroll 8
        for (int k = 0; k < 128; k++) {
            float a[8];
            #pragma unroll
            for (int r = 0; r < 8; r++) a[r] = Zout[r0 + r][k];
            float4 b = *(float4*)&Ws[k][c0];
            #pragma unroll
            for (int r = 0; r < 8; r++) {
                acc[r][0] += a[r] * b.x; acc[r][1] += a[r] * b.y;
                acc[r][2] += a[r] * b.z; acc[r][3] += a[r] * b.w;
            }
        }
        float4 bb = __ldg((const float4*)(pb2 + c0));
        #pragma unroll
        for (int r = 0; r < 8; r++) {
            float4 o;
            o.x = fmaxf(acc[r][0] + bb.x, 0.f);
            o.y = fmaxf(acc[r][1] + bb.y, 0.f);
            o.z = fmaxf(acc[r][2] + bb.z, 0.f);
            o.w = fmaxf(acc[r][3] + bb.w, 0.f);
            *(float4*)&Zin[r0 + r][c0] = o;
        }
    }
    __syncthreads();

    // --- stage 3: out = Zin @ pw3 + pb3 (dot per row) ---
    {
        int rr = t >> 2;     // 0..63
        int part = t & 3;    // 0..3 (consecutive lanes)
        float s = 0.f;
        #pragma unroll
        for (int j = 0; j < 32; j++) {
            int k = part * 32 + j;
            s += Zin[rr][k] * __ldg(pw3 + k);
        }
        s += __shfl_xor_sync(0xffffffffu, s, 1);
        s += __shfl_xor_sync(0xffffffffu, s, 2);
        if (part == 0 && p0 + rr < PP)
            out[p0 + rr] = s + __ldg(pb3);
    }
}

// ---------------------------------------------------------------------------
extern "C" void kernel_launch(void* const* d_in, const int* in_sizes, int n_in,
                              void* d_out, int out_size)
{
    const float* x     = (const float*)d_in[0];
    const int* src[3]  = {(const int*)d_in[1], (const int*)d_in[4], (const int*)d_in[7]};
    const int* dst[3]  = {(const int*)d_in[2], (const int*)d_in[5], (const int*)d_in[8]};
    const float* w[3]  = {(const float*)d_in[3], (const float*)d_in[6], (const float*)d_in[9]};
    const int* pos_src = (const int*)d_in[10];
    const int* pos_dst = (const int*)d_in[11];
    const int* neg_src = (const int*)d_in[12];
    const int* neg_dst = (const int*)d_in[13];
    const float* Wself[3]  = {(const float*)d_in[14], (const float*)d_in[17], (const float*)d_in[20]};
    const float* Wneigh[3] = {(const float*)d_in[15], (const float*)d_in[18], (const float*)d_in[21]};
    const float* bvec[3]   = {(const float*)d_in[16], (const float*)d_in[19], (const float*)d_in[22]};
    const float* pw1 = (const float*)d_in[23];
    const float* pb1 = (const float*)d_in[24];
    const float* pw2 = (const float*)d_in[25];
    const float* pb2 = (const float*)d_in[26];
    const float* pw3 = (const float*)d_in[27];
    const float* pb3 = (const float*)d_in[28];

    float* out = (float*)d_out;
    float* h_final = out + 2 * PP;   // output layout: [h_pos | h_neg | h]

    void *agg_p, *cnt_p, *hA_p, *hB_p;
    cudaGetSymbolAddress(&agg_p, g_agg);
    cudaGetSymbolAddress(&cnt_p, g_cnt);
    cudaGetSymbolAddress(&hA_p, g_hA);
    cudaGetSymbolAddress(&hB_p, g_hB);
    float* hA = (float*)hA_p;
    float* hB = (float*)hB_p;

    static bool attr_set = false;
    if (!attr_set) {
        cudaFuncSetAttribute(pred_kernel, cudaFuncAttributeMaxDynamicSharedMemorySize, SMEM_PRED);
        attr_set = true;
    }

    const int edge_blocks = (EE * 32 + 255) / 256;
    const int node_blocks = (NN + BM - 1) / BM;
    const int pred_blocks = (PP + 63) / 64;

    const float* layer_in[3]  = {x, hA, hB};
    float*       layer_out[3] = {hA, hB, h_final};

    for (int l = 0; l < 3; l++) {
        cudaMemsetAsync(agg_p, 0, (size_t)NN * D * sizeof(float));
        cudaMemsetAsync(cnt_p, 0, (size_t)NN * sizeof(float));
        edge_kernel<<<edge_blocks, 256>>>(src[l], dst[l], w[l], layer_in[l]);
        sage_node_kernel<<<node_blocks, 256>>>(layer_in[l], Wself[l], Wneigh[l],
                                               bvec[l], layer_out[l], l < 2 ? 1 : 0);
    }

    pred_kernel<<<pred_blocks, 256, SMEM_PRED>>>(h_final, pos_src, pos_dst,
        pw1, pb1, pw2, pb2, pw3, pb3, out);
    pred_kernel<<<pred_blocks, 256, SMEM_PRED>>>(h_final, neg_src, neg_dst,
        pw1, pb1, pw2, pb2, pw3, pb3, out + PP);
}

// round 3
// speedup vs baseline: 1.1559x; 1.1559x over previous
#include <cuda_runtime.h>
#include <cstdint>

#define NN 100000
#define EE 600000
#define PP 100000
#define D  128

__device__ float g_hA[(size_t)NN * D];
__device__ float g_hB[(size_t)NN * D];
__device__ float g_agg[(size_t)NN * D];
__device__ float g_cnt[NN];

// ---------------------------------------------------------------------------
// Edge scatter: agg[dst] += w * h[src], cnt[dst] += 1
// ---------------------------------------------------------------------------
__global__ void __launch_bounds__(256) edge_kernel(
    const int* __restrict__ src, const int* __restrict__ dst,
    const float* __restrict__ w, const float* __restrict__ h)
{
    int t = blockIdx.x * blockDim.x + threadIdx.x;
    int e = t >> 5;
    if (e >= EE) return;
    int lane = t & 31;
    int s = __ldg(src + e);
    int d = __ldg(dst + e);
    float we = __ldg(w + e);
    float4 v = __ldg((const float4*)(h + (size_t)s * D) + lane);
    v.x *= we; v.y *= we; v.z *= we; v.w *= we;
    float* a = g_agg + (size_t)d * D + lane * 4;
    asm volatile("red.global.add.v4.f32 [%0], {%1,%2,%3,%4};"
                 :: "l"(a), "f"(v.x), "f"(v.y), "f"(v.z), "f"(v.w) : "memory");
    if (lane == 0) atomicAdd(g_cnt + d, 1.0f);
}

// ---------------------------------------------------------------------------
// Fused SAGE node update: out = [h | agg/max(cnt,1)] @ [Wself;Wneigh] + b
// 128x128 tile, BK=16, 256 threads, 8x8 micro-tile, transposed-A smem,
// register prefetch of next K-tile.
// ---------------------------------------------------------------------------
#define BMN 128
#define BKN 16
#define APAD 132   // As row stride (floats), 16B aligned, low conflict

__global__ void __launch_bounds__(256, 2) sage_node_kernel(
    const float* __restrict__ h_in,
    const float* __restrict__ Wself, const float* __restrict__ Wneigh,
    const float* __restrict__ bias,
    float* __restrict__ h_out, int do_relu)
{
    __shared__ float As[BKN][APAD];   // [k][m] transposed
    __shared__ float Bs[BKN][128];    // [k][n]
    __shared__ float rcp_s[BMN];

    int t = threadIdx.x;
    int row_blk = blockIdx.x * BMN;

    if (t < BMN) {
        int g = row_blk + t;
        float c = (g < NN) ? g_cnt[g] : 1.0f;
        rcp_s[t] = 1.0f / fmaxf(c, 1.0f);
    }

    int tm = t >> 4;        // 0..15
    int tn = t & 15;        // 0..15
    int r0 = tm * 8;
    int c0 = tn * 4;        // second col block at 64 + tn*4

    float acc[8][8];
    #pragma unroll
    for (int r = 0; r < 8; r++)
        #pragma unroll
        for (int c = 0; c < 8; c++) acc[r][c] = 0.0f;

    // prefetch registers
    float4 pa[2], pb[2];
    int arow[2];

    auto load_tile = [&](int kb, float4* ra, float4* rb, int* rrow) {
        const float* Abase = (kb < 8) ? h_in : g_agg;
        int koff = (kb < 8) ? kb * BKN : kb * BKN - 128;
        #pragma unroll
        for (int i = 0; i < 2; i++) {
            int idx = t + i * 256;          // 0..511
            int ar = idx >> 2;              // 0..127
            int aq = idx & 3;               // 0..3
            rrow[i] = ar;
            int g = row_blk + ar;
            float4 v = make_float4(0.f, 0.f, 0.f, 0.f);
            if (g < NN)
                v = __ldg((const float4*)(Abase + (size_t)g * D + koff) + aq);
            ra[i] = v;
        }
        #pragma unroll
        for (int i = 0; i < 2; i++) {
            int idx = t + i * 256;
            int kk = idx >> 5;              // 0..15
            int j4 = idx & 31;              // 0..31
            int kg = kb * BKN + kk;
            const float* W = (kg < 128) ? Wself : Wneigh;
            rb[i] = __ldg((const float4*)(W + (size_t)(kg & 127) * D) + j4);
        }
    };

    load_tile(0, pa, pb, arow);
    __syncthreads();   // rcp_s ready

    #pragma unroll 1
    for (int kb = 0; kb < 16; kb++) {
        bool is_agg = (kb >= 8);
        // store prefetched tile to smem
        #pragma unroll
        for (int i = 0; i < 2; i++) {
            int idx = t + i * 256;
            int aq = idx & 3;
            float sc = is_agg ? rcp_s[arow[i]] : 1.0f;
            As[aq * 4 + 0][arow[i]] = pa[i].x * sc;
            As[aq * 4 + 1][arow[i]] = pa[i].y * sc;
            As[aq * 4 + 2][arow[i]] = pa[i].z * sc;
            As[aq * 4 + 3][arow[i]] = pa[i].w * sc;
        }
        #pragma unroll
        for (int i = 0; i < 2; i++) {
            int idx = t + i * 256;
            int kk = idx >> 5;
            int j4 = idx & 31;
            *(float4*)&Bs[kk][j4 * 4] = pb[i];
        }
        __syncthreads();

        if (kb + 1 < 16) load_tile(kb + 1, pa, pb, arow);

        #pragma unroll
        for (int k = 0; k < BKN; k++) {
            float4 a0 = *(float4*)&As[k][r0];
            float4 a1 = *(float4*)&As[k][r0 + 4];
            float4 b0 = *(float4*)&Bs[k][c0];
            float4 b1 = *(float4*)&Bs[k][64 + c0];
            float av[8] = {a0.x, a0.y, a0.z, a0.w, a1.x, a1.y, a1.z, a1.w};
            #pragma unroll
            for (int r = 0; r < 8; r++) {
                acc[r][0] += av[r] * b0.x; acc[r][1] += av[r] * b0.y;
                acc[r][2] += av[r] * b0.z; acc[r][3] += av[r] * b0.w;
                acc[r][4] += av[r] * b1.x; acc[r][5] += av[r] * b1.y;
                acc[r][6] += av[r] * b1.z; acc[r][7] += av[r] * b1.w;
            }
        }
        __syncthreads();
    }

    float4 bb0 = __ldg((const float4*)(bias + c0));
    float4 bb1 = __ldg((const float4*)(bias + 64 + c0));
    #pragma unroll
    for (int r = 0; r < 8; r++) {
        int g = row_blk + r0 + r;
        if (g < NN) {
            float4 o0, o1;
            o0.x = acc[r][0] + bb0.x; o0.y = acc[r][1] + bb0.y;
            o0.z = acc[r][2] + bb0.z; o0.w = acc[r][3] + bb0.w;
            o1.x = acc[r][4] + bb1.x; o1.y = acc[r][5] + bb1.y;
            o1.z = acc[r][6] + bb1.z; o1.w = acc[r][7] + bb1.w;
            if (do_relu) {
                o0.x = fmaxf(o0.x, 0.f); o0.y = fmaxf(o0.y, 0.f);
                o0.z = fmaxf(o0.z, 0.f); o0.w = fmaxf(o0.w, 0.f);
                o1.x = fmaxf(o1.x, 0.f); o1.y = fmaxf(o1.y, 0.f);
                o1.z = fmaxf(o1.z, 0.f); o1.w = fmaxf(o1.w, 0.f);
            }
            *(float4*)(h_out + (size_t)g * D + c0) = o0;
            *(float4*)(h_out + (size_t)g * D + 64 + c0) = o1;
        }
    }
}

// ---------------------------------------------------------------------------
// Fused link predictor, one launch for pos+neg.
// 128 pairs/block, Z kept transposed in smem (Zt[feat][pair]), 8x8 micro-tile,
// weights streamed in BK=32 chunks, stage output written back in place.
// ---------------------------------------------------------------------------
#define PB 782           // blocks per pair set: ceil(100000/128)
#define ZT_PAD 132
#define PRED_BK 32
#define SMEM_PRED ((128 * ZT_PAD + PRED_BK * 128) * 4)

__global__ void __launch_bounds__(256, 2) pred_kernel(
    const float* __restrict__ h,
    const int* __restrict__ pos_a, const int* __restrict__ pos_b,
    const int* __restrict__ neg_a, const int* __restrict__ neg_b,
    const float* __restrict__ pw1, const float* __restrict__ pb1,
    const float* __restrict__ pw2, const float* __restrict__ pb2,
    const float* __restrict__ pw3, const float* __restrict__ pb3,
    float* __restrict__ out)
{
    extern __shared__ float sm[];
    float (*Zt)[ZT_PAD] = (float(*)[ZT_PAD])sm;            // [128 feat][132]
    float (*Bs)[128]    = (float(*)[128])(sm + 128 * ZT_PAD);

    int t = threadIdx.x;
    bool is_neg = blockIdx.x >= PB;
    int p0 = (is_neg ? (blockIdx.x - PB) : blockIdx.x) * 128;
    const int* ia = is_neg ? neg_a : pos_a;
    const int* ib = is_neg ? neg_b : pos_b;
    float* outp = out + (is_neg ? PP : 0);

    // --- stage 0: Zt[:, pair] = h[ia]*h[ib] (transposed store) ---
    {
        int zrow = t >> 1;          // pair 0..127
        int half = t & 1;           // feature half
        int gp = p0 + zrow;
        bool valid = gp < PP;
        int sa = valid ? __ldg(ia + gp) : 0;
        int sb = valid ? __ldg(ib + gp) : 0;
        const float4* ha = (const float4*)(h + (size_t)sa * D) + half * 16;
        const float4* hb = (const float4*)(h + (size_t)sb * D) + half * 16;
        #pragma unroll
        for (int i = 0; i < 16; i++) {
            float4 va = __ldg(ha + i);
            float4 vb = __ldg(hb + i);
            int f = half * 64 + i * 4;
            Zt[f + 0][zrow] = va.x * vb.x;
            Zt[f + 1][zrow] = va.y * vb.y;
            Zt[f + 2][zrow] = va.z * vb.z;
            Zt[f + 3][zrow] = va.w * vb.w;
        }
    }

    int tm = t >> 4, tn = t & 15;
    int r0 = tm * 8, c0 = tn * 4;

    // Two MLP stages
    #pragma unroll 1
    for (int stage = 0; stage < 2; stage++) {
        const float* W = stage ? pw2 : pw1;
        const float* B = stage ? pb2 : pb1;

        float acc[8][8];
        #pragma unroll
        for (int r = 0; r < 8; r++)
            #pragma unroll
            for (int c = 0; c < 8; c++) acc[r][c] = 0.f;

        #pragma unroll 1
        for (int kb = 0; kb < 128; kb += PRED_BK) {
            __syncthreads();    // Bs free / Zt ready
            #pragma unroll
            for (int i = 0; i < 4; i++) {
                int idx = t + i * 256;       // 0..1023
                int kk = idx >> 5;           // 0..31
                int j4 = idx & 31;
                *(float4*)&Bs[kk][j4 * 4] =
                    __ldg((const float4*)(W + (size_t)(kb + kk) * D) + j4);
            }
            __syncthreads();

            #pragma unroll
            for (int k = 0; k < PRED_BK; k++) {
                float4 a0 = *(float4*)&Zt[kb + k][r0];
                float4 a1 = *(float4*)&Zt[kb + k][r0 + 4];
                float4 b0 = *(float4*)&Bs[k][c0];
                float4 b1 = *(float4*)&Bs[k][64 + c0];
                float av[8] = {a0.x, a0.y, a0.z, a0.w, a1.x, a1.y, a1.z, a1.w};
                #pragma unroll
                for (int r = 0; r < 8; r++) {
                    acc[r][0] += av[r] * b0.x; acc[r][1] += av[r] * b0.y;
                    acc[r][2] += av[r] * b0.z; acc[r][3] += av[r] * b0.w;
                    acc[r][4] += av[r] * b1.x; acc[r][5] += av[r] * b1.y;
                    acc[r][6] += av[r] * b1.z; acc[r][7] += av[r] * b1.w;
                }
            }
        }

        // bias + relu, write back transposed into Zt
        float4 bb0 = __ldg((const float4*)(B + c0));
        float4 bb1 = __ldg((const float4*)(B + 64 + c0));
        __syncthreads();   // everyone done reading Zt
        #pragma unroll
        for (int r = 0; r < 8; r++) {
            float v[8];
            v[0] = fmaxf(acc[r][0] + bb0.x, 0.f);
            v[1] = fmaxf(acc[r][1] + bb0.y, 0.f);
            v[2] = fmaxf(acc[r][2] + bb0.z, 0.f);
            v[3] = fmaxf(acc[r][3] + bb0.w, 0.f);
            v[4] = fmaxf(acc[r][4] + bb1.x, 0.f);
            v[5] = fmaxf(acc[r][5] + bb1.y, 0.f);
            v[6] = fmaxf(acc[r][6] + bb1.z, 0.f);
            v[7] = fmaxf(acc[r][7] + bb1.w, 0.f);
            #pragma unroll
            for (int c = 0; c < 4; c++) {
                Zt[c0 + c][r0 + r] = v[c];
                Zt[64 + c0 + c][r0 + r] = v[4 + c];
            }
        }
        __syncthreads();
    }

    // --- stage 3: out = Zt^T @ pw3 + pb3 ---
    {
        int rr = t >> 1;       // pair 0..127
        int part = t & 1;
        float s = 0.f;
        #pragma unroll
        for (int j = 0; j < 64; j++) {
            int k = part * 64 + j;
            s += Zt[k][rr] * __ldg(pw3 + k);
        }
        s += __shfl_xor_sync(0xffffffffu, s, 1);
        if (part == 0 && p0 + rr < PP)
            outp[p0 + rr] = s + __ldg(pb3);
    }
}

// ---------------------------------------------------------------------------
extern "C" void kernel_launch(void* const* d_in, const int* in_sizes, int n_in,
                              void* d_out, int out_size)
{
    const float* x     = (const float*)d_in[0];
    const int* src[3]  = {(const int*)d_in[1], (const int*)d_in[4], (const int*)d_in[7]};
    const int* dst[3]  = {(const int*)d_in[2], (const int*)d_in[5], (const int*)d_in[8]};
    const float* w[3]  = {(const float*)d_in[3], (const float*)d_in[6], (const float*)d_in[9]};
    const int* pos_src = (const int*)d_in[10];
    const int* pos_dst = (const int*)d_in[11];
    const int* neg_src = (const int*)d_in[12];
    const int* neg_dst = (const int*)d_in[13];
    const float* Wself[3]  = {(const float*)d_in[14], (const float*)d_in[17], (const float*)d_in[20]};
    const float* Wneigh[3] = {(const float*)d_in[15], (const float*)d_in[18], (const float*)d_in[21]};
    const float* bvec[3]   = {(const float*)d_in[16], (const float*)d_in[19], (const float*)d_in[22]};
    const float* pw1 = (const float*)d_in[23];
    const float* pb1 = (const float*)d_in[24];
    const float* pw2 = (const float*)d_in[25];
    const float* pb2 = (const float*)d_in[26];
    const float* pw3 = (const float*)d_in[27];
    const float* pb3 = (const float*)d_in[28];

    float* out = (float*)d_out;
    float* h_final = out + 2 * PP;   // output layout: [h_pos | h_neg | h]

    void *agg_p, *cnt_p, *hA_p, *hB_p;
    cudaGetSymbolAddress(&agg_p, g_agg);
    cudaGetSymbolAddress(&cnt_p, g_cnt);
    cudaGetSymbolAddress(&hA_p, g_hA);
    cudaGetSymbolAddress(&hB_p, g_hB);
    float* hA = (float*)hA_p;
    float* hB = (float*)hB_p;

    static bool attr_set = false;
    if (!attr_set) {
        cudaFuncSetAttribute(pred_kernel, cudaFuncAttributeMaxDynamicSharedMemorySize, SMEM_PRED);
        attr_set = true;
    }

    const int edge_blocks = (EE * 32 + 255) / 256;
    const int node_blocks = (NN + BMN - 1) / BMN;

    const float* layer_in[3]  = {x, hA, hB};
    float*       layer_out[3] = {hA, hB, h_final};

    for (int l = 0; l < 3; l++) {
        cudaMemsetAsync(agg_p, 0, (size_t)NN * D * sizeof(float));
        cudaMemsetAsync(cnt_p, 0, (size_t)NN * sizeof(float));
        edge_kernel<<<edge_blocks, 256>>>(src[l], dst[l], w[l], layer_in[l]);
        sage_node_kernel<<<node_blocks, 256>>>(layer_in[l], Wself[l], Wneigh[l],
                                               bvec[l], layer_out[l], l < 2 ? 1 : 0);
    }

    pred_kernel<<<2 * PB, 256, SMEM_PRED>>>(h_final, pos_src, pos_dst,
        neg_src, neg_dst, pw1, pb1, pw2, pb2, pw3, pb3, out);
}